// round 2
// baseline (speedup 1.0000x reference)
#include <cuda_runtime.h>
#include <cuda_bf16.h>
#include <cstdint>

#define S_   1024
#define H_   1024
#define B_   4
#define NH_  16
#define D_   64
#define BS_  4096
#define BH_  64

// ---------------- scratch (no allocs allowed) ----------------
__device__ float g_q[BS_ * H_];
__device__ float g_k[BS_ * H_];
__device__ float g_v[BS_ * H_];
__device__ float g_sc[(size_t)BH_ * S_ * S_];   // 256 MB scores/probs
__device__ float g_ctx[BS_ * H_];
__device__ float g_y[BS_ * H_];

// bf16 split buffers
__device__ __nv_bfloat16 g_xh[BS_ * H_], g_xl[BS_ * H_];
__device__ __nv_bfloat16 g_wqh[H_ * H_], g_wql[H_ * H_];
__device__ __nv_bfloat16 g_wkh[H_ * H_], g_wkl[H_ * H_];
__device__ __nv_bfloat16 g_wvh[H_ * H_], g_wvl[H_ * H_];
__device__ __nv_bfloat16 g_woh[H_ * H_], g_wol[H_ * H_];
__device__ __nv_bfloat16 g_ch[BS_ * H_], g_cl[BS_ * H_];

// ---------------- fp32 -> (hi,lo) bf16 split ---------------------------------------
__global__ void __launch_bounds__(256) split_kernel(const float* __restrict__ in,
                                                    __nv_bfloat16* __restrict__ hi,
                                                    __nv_bfloat16* __restrict__ lo,
                                                    int n4)
{
    int i = blockIdx.x * 256 + threadIdx.x;
    if (i >= n4) return;
    float4 a = ((const float4*)in)[i];
    __nv_bfloat16 h0 = __float2bfloat16(a.x);
    __nv_bfloat16 h1 = __float2bfloat16(a.y);
    __nv_bfloat16 h2 = __float2bfloat16(a.z);
    __nv_bfloat16 h3 = __float2bfloat16(a.w);
    __nv_bfloat162 hh0; hh0.x = h0; hh0.y = h1;
    __nv_bfloat162 hh1; hh1.x = h2; hh1.y = h3;
    ((__nv_bfloat162*)hi)[i * 2 + 0] = hh0;
    ((__nv_bfloat162*)hi)[i * 2 + 1] = hh1;
    __nv_bfloat162 ll0, ll1;
    ll0.x = __float2bfloat16(a.x - __bfloat162float(h0));
    ll0.y = __float2bfloat16(a.y - __bfloat162float(h1));
    ll1.x = __float2bfloat16(a.z - __bfloat162float(h2));
    ll1.y = __float2bfloat16(a.w - __bfloat162float(h3));
    ((__nv_bfloat162*)lo)[i * 2 + 0] = ll0;
    ((__nv_bfloat162*)lo)[i * 2 + 1] = ll1;
}

// ---------------- mma helpers -------------------------------------------------------
__device__ __forceinline__ uint32_t s2u(const void* p)
{
    return (uint32_t)__cvta_generic_to_shared(p);
}
__device__ __forceinline__ void ldm4(uint32_t* r, uint32_t addr)
{
    asm volatile("ldmatrix.sync.aligned.m8n8.x4.shared.b16 {%0,%1,%2,%3}, [%4];"
                 : "=r"(r[0]), "=r"(r[1]), "=r"(r[2]), "=r"(r[3]) : "r"(addr));
}
__device__ __forceinline__ void mma16816(float* c, const uint32_t* a, const uint32_t* b)
{
    asm volatile("mma.sync.aligned.m16n8k16.row.col.f32.bf16.bf16.f32 "
                 "{%0,%1,%2,%3}, {%4,%5,%6,%7}, {%8,%9}, {%0,%1,%2,%3};"
                 : "+f"(c[0]), "+f"(c[1]), "+f"(c[2]), "+f"(c[3])
                 : "r"(a[0]), "r"(a[1]), "r"(a[2]), "r"(a[3]), "r"(b[0]), "r"(b[1]));
}

// ---------------- split-bf16 GEMM NT via HMMA --------------------------------------
// C[i,j] = sum_k A[i,k]*B[j,k] + bias[j] (+resid[i,j]); K=N=1024, M=4096.
// block 128x128, 8 warps (2x4), warp 64x32, 3 mma passes (hh, hl, lh).
#define KT   32
#define LDS_ 40   // KT + 8 pad (halves); row stride 80 B

template <bool RESID>
__global__ void __launch_bounds__(256) gemm_mma(
    const __nv_bfloat16* __restrict__ Ah, const __nv_bfloat16* __restrict__ Al,
    const __nv_bfloat16* __restrict__ Bh0, const __nv_bfloat16* __restrict__ Bl0,
    const __nv_bfloat16* __restrict__ Bh1, const __nv_bfloat16* __restrict__ Bl1,
    const __nv_bfloat16* __restrict__ Bh2, const __nv_bfloat16* __restrict__ Bl2,
    const float* __restrict__ bias0, const float* __restrict__ bias1,
    const float* __restrict__ bias2,
    float* __restrict__ O0, float* __restrict__ O1, float* __restrict__ O2,
    const float* __restrict__ resid)
{
    __shared__ __nv_bfloat16 sAh[128 * LDS_], sAl[128 * LDS_];
    __shared__ __nv_bfloat16 sBh[128 * LDS_], sBl[128 * LDS_];

    const int z = blockIdx.z;
    const __nv_bfloat16* Bh = (z == 0) ? Bh0 : (z == 1) ? Bh1 : Bh2;
    const __nv_bfloat16* Bl = (z == 0) ? Bl0 : (z == 1) ? Bl1 : Bl2;
    const float* bias = (z == 0) ? bias0 : (z == 1) ? bias1 : bias2;
    float* O = (z == 0) ? O0 : (z == 1) ? O1 : O2;

    const int tid = threadIdx.x;
    const int lane = tid & 31, wid = tid >> 5;
    const int wm = wid >> 2, wn = wid & 3;
    const int bM = blockIdx.y * 128, bN = blockIdx.x * 128;

    float acc[4][4][4] = {};

    const int q8 = lane >> 3, r8 = lane & 7;
    const int arowL = wm * 64 + (q8 & 1) * 8 + r8;   // + mt*16
    const int browL = wn * 32 + (q8 >> 1) * 8 + r8;  // + p*16
    const int acolL = (q8 >> 1) * 8;                 // + ks
    const int bcolL = (q8 & 1) * 8;                  // + ks

    for (int k0 = 0; k0 < H_; k0 += KT) {
        uint4 va[2], vla[2], vb[2], vlb[2];
#pragma unroll
        for (int i = 0; i < 2; i++) {
            const int c = tid + 256 * i;
            const int row = c >> 2;
            const int cc = (c & 3) * 8;
            va[i]  = *(const uint4*)(Ah + (size_t)(bM + row) * H_ + k0 + cc);
            vla[i] = *(const uint4*)(Al + (size_t)(bM + row) * H_ + k0 + cc);
            vb[i]  = *(const uint4*)(Bh + (size_t)(bN + row) * H_ + k0 + cc);
            vlb[i] = *(const uint4*)(Bl + (size_t)(bN + row) * H_ + k0 + cc);
        }
        __syncthreads();
#pragma unroll
        for (int i = 0; i < 2; i++) {
            const int c = tid + 256 * i;
            const int row = c >> 2;
            const int cc = (c & 3) * 8;
            *(uint4*)(sAh + row * LDS_ + cc) = va[i];
            *(uint4*)(sAl + row * LDS_ + cc) = vla[i];
            *(uint4*)(sBh + row * LDS_ + cc) = vb[i];
            *(uint4*)(sBl + row * LDS_ + cc) = vlb[i];
        }
        __syncthreads();

#pragma unroll
        for (int ks = 0; ks < KT; ks += 16) {
            uint32_t afh[4][4], afl[4][4];
#pragma unroll
            for (int mt = 0; mt < 4; mt++) {
                const int ro = (arowL + mt * 16) * LDS_ + acolL + ks;
                ldm4(afh[mt], s2u(sAh + ro));
                ldm4(afl[mt], s2u(sAl + ro));
            }
            uint32_t bfh[2][4], bfl[2][4];
#pragma unroll
            for (int p = 0; p < 2; p++) {
                const int ro = (browL + p * 16) * LDS_ + bcolL + ks;
                ldm4(bfh[p], s2u(sBh + ro));
                ldm4(bfl[p], s2u(sBl + ro));
            }
#pragma unroll
            for (int mt = 0; mt < 4; mt++)
#pragma unroll
                for (int nt = 0; nt < 4; nt++) {
                    const uint32_t* bh = &bfh[nt >> 1][(nt & 1) * 2];
                    const uint32_t* bl = &bfl[nt >> 1][(nt & 1) * 2];
                    mma16816(acc[mt][nt], afh[mt], bh);
                    mma16816(acc[mt][nt], afh[mt], bl);
                    mma16816(acc[mt][nt], afl[mt], bh);
                }
        }
    }

    const int crow0 = bM + wm * 64 + (lane >> 2);
    const int ccol0 = bN + wn * 32 + (lane & 3) * 2;
#pragma unroll
    for (int mt = 0; mt < 4; mt++) {
        const int r0 = crow0 + mt * 16;
#pragma unroll
        for (int nt = 0; nt < 4; nt++) {
            const int c0 = ccol0 + nt * 8;
            float f0 = acc[mt][nt][0] + bias[c0];
            float f1 = acc[mt][nt][1] + bias[c0 + 1];
            float f2 = acc[mt][nt][2] + bias[c0];
            float f3 = acc[mt][nt][3] + bias[c0 + 1];
            if (RESID) {
                f0 += resid[(size_t)r0 * H_ + c0];
                f1 += resid[(size_t)r0 * H_ + c0 + 1];
                f2 += resid[(size_t)(r0 + 8) * H_ + c0];
                f3 += resid[(size_t)(r0 + 8) * H_ + c0 + 1];
            }
            O[(size_t)r0 * H_ + c0]           = f0;
            O[(size_t)r0 * H_ + c0 + 1]       = f1;
            O[(size_t)(r0 + 8) * H_ + c0]     = f2;
            O[(size_t)(r0 + 8) * H_ + c0 + 1] = f3;
        }
    }
}

// ---------------- scores: qk^T + (q+k)·dist_emb[l-r+1023], scaled + mask ----------
__global__ void __launch_bounds__(256) scores_kernel(
    const float* __restrict__ q, const float* __restrict__ k,
    const float* __restrict__ dist, const float* __restrict__ mask,
    float* __restrict__ sc)
{
    extern __shared__ float sm[];
    float* sQ = sm;                 // [64][65]
    float* sK = sm + 64 * 65;       // [64][65]
    float* sP = sm + 128 * 65;      // [127][65]

    const int l0 = blockIdx.x * 64;
    const int r0 = blockIdx.y * 64;
    const int bh = blockIdx.z;
    const int b = bh >> 4, h = bh & 15;
    const int tid = threadIdx.x;

    for (int idx = tid; idx < 64 * 16; idx += 256) {
        const int row = idx >> 4, c = (idx & 15) * 4;
        float4 qa = *(const float4*)(q + (size_t)(b * S_ + l0 + row) * H_ + h * D_ + c);
        float4 ka = *(const float4*)(k + (size_t)(b * S_ + r0 + row) * H_ + h * D_ + c);
        sQ[row * 65 + c + 0] = qa.x; sQ[row * 65 + c + 1] = qa.y;
        sQ[row * 65 + c + 2] = qa.z; sQ[row * 65 + c + 3] = qa.w;
        sK[row * 65 + c + 0] = ka.x; sK[row * 65 + c + 1] = ka.y;
        sK[row * 65 + c + 2] = ka.z; sK[row * 65 + c + 3] = ka.w;
    }
    const int prow0 = l0 - r0 + 960;
    for (int idx = tid; idx < 127 * 16; idx += 256) {
        const int t = idx >> 4, c = (idx & 15) * 4;
        float4 pa = *(const float4*)(dist + (size_t)(prow0 + t) * D_ + c);
        sP[t * 65 + c + 0] = pa.x; sP[t * 65 + c + 1] = pa.y;
        sP[t * 65 + c + 2] = pa.z; sP[t * 65 + c + 3] = pa.w;
    }
    __syncthreads();

    const int ty = tid >> 4, tx = tid & 15;
    const int tb = ty - tx + 63;
    float acc[4][4] = {};

#pragma unroll 2
    for (int d = 0; d < 64; d++) {
        float qv[4], kv[4], pv[7];
#pragma unroll
        for (int m = 0; m < 4; m++) qv[m] = sQ[(ty + 16 * m) * 65 + d];
#pragma unroll
        for (int n = 0; n < 4; n++) kv[n] = sK[(tx + 16 * n) * 65 + d];
#pragma unroll
        for (int u = 0; u < 7; u++) pv[u] = sP[(tb + 16 * (u - 3)) * 65 + d];
#pragma unroll
        for (int m = 0; m < 4; m++)
#pragma unroll
            for (int n = 0; n < 4; n++) {
                acc[m][n] = fmaf(qv[m], kv[n], acc[m][n]);
                acc[m][n] = fmaf(qv[m] + kv[n], pv[m - n + 3], acc[m][n]);
            }
    }

#pragma unroll
    for (int m = 0; m < 4; m++) {
        const int l = l0 + ty + 16 * m;
#pragma unroll
        for (int n = 0; n < 4; n++) {
            const int r = r0 + tx + 16 * n;
            sc[((size_t)bh * S_ + l) * S_ + r] = acc[m][n] * 0.125f + mask[b * S_ + r];
        }
    }
}

// ---------------- softmax over last dim (rows of 1024) -----------------------------
__global__ void __launch_bounds__(256) softmax_kernel(float* __restrict__ sc)
{
    __shared__ float sred[8];
    __shared__ float sbc;
    const size_t row = blockIdx.x;
    float* p = sc + row * S_;
    const int tid = threadIdx.x;
    const int lane = tid & 31, wid = tid >> 5;

    float4 v = ((const float4*)p)[tid];

    float m = fmaxf(fmaxf(v.x, v.y), fmaxf(v.z, v.w));
#pragma unroll
    for (int o = 16; o > 0; o >>= 1) m = fmaxf(m, __shfl_xor_sync(~0u, m, o));
    if (lane == 0) sred[wid] = m;
    __syncthreads();
    if (tid == 0) {
        float t = sred[0];
#pragma unroll
        for (int i = 1; i < 8; i++) t = fmaxf(t, sred[i]);
        sbc = t;
    }
    __syncthreads();
    const float bm = sbc;

    float e0 = __expf(v.x - bm), e1 = __expf(v.y - bm);
    float e2 = __expf(v.z - bm), e3 = __expf(v.w - bm);
    float s = e0 + e1 + e2 + e3;
#pragma unroll
    for (int o = 16; o > 0; o >>= 1) s += __shfl_xor_sync(~0u, s, o);
    if (lane == 0) sred[wid] = s;
    __syncthreads();
    if (tid == 0) {
        float t = 0.f;
#pragma unroll
        for (int i = 0; i < 8; i++) t += sred[i];
        sbc = t;
    }
    __syncthreads();
    const float inv = 1.f / sbc;

    v.x = e0 * inv; v.y = e1 * inv; v.z = e2 * inv; v.w = e3 * inv;
    ((float4*)p)[tid] = v;
}

// ---------------- ctx = probs @ V ---------------------------------------------------
__global__ void __launch_bounds__(256) ctx_kernel(const float* __restrict__ probs,
                                                  const float* __restrict__ v,
                                                  float* __restrict__ ctx)
{
    __shared__ float sPb[64 * 65];
    __shared__ float sV[64 * 65];
    const int l0 = blockIdx.x * 64;
    const int bh = blockIdx.y;
    const int b = bh >> 4, h = bh & 15;
    const int tid = threadIdx.x;
    const int ty = tid >> 4, tx = tid & 15;

    float acc[4][4] = {};

    for (int r0 = 0; r0 < S_; r0 += 64) {
        __syncthreads();
        for (int idx = tid; idx < 64 * 16; idx += 256) {
            const int row = idx >> 4, c = (idx & 15) * 4;
            float4 pa = *(const float4*)(probs + ((size_t)bh * S_ + l0 + row) * S_ + r0 + c);
            float4 va = *(const float4*)(v + (size_t)(b * S_ + r0 + row) * H_ + h * D_ + c);
            sPb[row * 65 + c + 0] = pa.x; sPb[row * 65 + c + 1] = pa.y;
            sPb[row * 65 + c + 2] = pa.z; sPb[row * 65 + c + 3] = pa.w;
            sV[row * 65 + c + 0] = va.x; sV[row * 65 + c + 1] = va.y;
            sV[row * 65 + c + 2] = va.z; sV[row * 65 + c + 3] = va.w;
        }
        __syncthreads();
#pragma unroll 4
        for (int rr = 0; rr < 64; rr++) {
            float pvv[4], vv[4];
#pragma unroll
            for (int m = 0; m < 4; m++) pvv[m] = sPb[(ty + 16 * m) * 65 + rr];
#pragma unroll
            for (int n = 0; n < 4; n++) vv[n] = sV[rr * 65 + tx + 16 * n];
#pragma unroll
            for (int m = 0; m < 4; m++)
#pragma unroll
                for (int n = 0; n < 4; n++)
                    acc[m][n] = fmaf(pvv[m], vv[n], acc[m][n]);
        }
    }

#pragma unroll
    for (int m = 0; m < 4; m++) {
        const int l = l0 + ty + 16 * m;
#pragma unroll
        for (int n = 0; n < 4; n++)
            ctx[(size_t)(b * S_ + l) * H_ + h * D_ + tx + 16 * n] = acc[m][n];
    }
}

// ---------------- LayerNorm over H per token ---------------------------------------
__global__ void __launch_bounds__(256) ln_kernel(const float* __restrict__ y,
                                                 const float* __restrict__ g,
                                                 const float* __restrict__ bb,
                                                 float* __restrict__ out)
{
    __shared__ float sred[8];
    __shared__ float sbc;
    const size_t row = blockIdx.x;
    const int tid = threadIdx.x;
    const int lane = tid & 31, wid = tid >> 5;

    float4 v = ((const float4*)(y + row * H_))[tid];

    float s = v.x + v.y + v.z + v.w;
#pragma unroll
    for (int o = 16; o > 0; o >>= 1) s += __shfl_xor_sync(~0u, s, o);
    if (lane == 0) sred[wid] = s;
    __syncthreads();
    if (tid == 0) {
        float t = 0.f;
#pragma unroll
        for (int i = 0; i < 8; i++) t += sred[i];
        sbc = t;
    }
    __syncthreads();
    const float mu = sbc * (1.f / H_);

    float dx = v.x - mu, dy = v.y - mu, dz = v.z - mu, dw = v.w - mu;
    float qq = dx * dx + dy * dy + dz * dz + dw * dw;
#pragma unroll
    for (int o = 16; o > 0; o >>= 1) qq += __shfl_xor_sync(~0u, qq, o);
    if (lane == 0) sred[wid] = qq;
    __syncthreads();
    if (tid == 0) {
        float t = 0.f;
#pragma unroll
        for (int i = 0; i < 8; i++) t += sred[i];
        sbc = t;
    }
    __syncthreads();
    const float rstd = rsqrtf(sbc * (1.f / H_) + 1e-12f);

    float4 gg = ((const float4*)g)[tid];
    float4 bt = ((const float4*)bb)[tid];
    float4 o;
    o.x = dx * rstd * gg.x + bt.x;
    o.y = dy * rstd * gg.y + bt.y;
    o.z = dz * rstd * gg.z + bt.z;
    o.w = dw * rstd * gg.w + bt.w;
    ((float4*)(out + row * H_))[tid] = o;
}

// ---------------- launch -----------------------------------------------------------
extern "C" void kernel_launch(void* const* d_in, const int* in_sizes, int n_in,
                              void* d_out, int out_size)
{
    (void)in_sizes; (void)n_in; (void)out_size;
    const float* x    = (const float*)d_in[0];
    const float* mask = (const float*)d_in[1];
    const float* Wq   = (const float*)d_in[2];
    const float* bq   = (const float*)d_in[3];
    const float* Wk   = (const float*)d_in[4];
    const float* bk   = (const float*)d_in[5];
    const float* Wv   = (const float*)d_in[6];
    const float* bv   = (const float*)d_in[7];
    const float* de   = (const float*)d_in[8];
    const float* Wo   = (const float*)d_in[9];
    const float* bo   = (const float*)d_in[10];
    const float* lng  = (const float*)d_in[11];
    const float* lnb  = (const float*)d_in[12];
    float* out = (float*)d_out;

    float *q, *k, *v, *sc, *ctx, *y;
    cudaGetSymbolAddress((void**)&q,   g_q);
    cudaGetSymbolAddress((void**)&k,   g_k);
    cudaGetSymbolAddress((void**)&v,   g_v);
    cudaGetSymbolAddress((void**)&sc,  g_sc);
    cudaGetSymbolAddress((void**)&ctx, g_ctx);
    cudaGetSymbolAddress((void**)&y,   g_y);

    __nv_bfloat16 *xh, *xl, *wqh, *wql, *wkh, *wkl, *wvh, *wvl, *woh, *wol, *ch, *cl;
    cudaGetSymbolAddress((void**)&xh, g_xh);   cudaGetSymbolAddress((void**)&xl, g_xl);
    cudaGetSymbolAddress((void**)&wqh, g_wqh); cudaGetSymbolAddress((void**)&wql, g_wql);
    cudaGetSymbolAddress((void**)&wkh, g_wkh); cudaGetSymbolAddress((void**)&wkl, g_wkl);
    cudaGetSymbolAddress((void**)&wvh, g_wvh); cudaGetSymbolAddress((void**)&wvl, g_wvl);
    cudaGetSymbolAddress((void**)&woh, g_woh); cudaGetSymbolAddress((void**)&wol, g_wol);
    cudaGetSymbolAddress((void**)&ch, g_ch);   cudaGetSymbolAddress((void**)&cl, g_cl);

    const int NX4 = BS_ * H_ / 4;   // 1M
    const int NW4 = H_ * H_ / 4;    // 256K
    split_kernel<<<NX4 / 256, 256>>>(x,  xh,  xl,  NX4);
    split_kernel<<<NW4 / 256, 256>>>(Wq, wqh, wql, NW4);
    split_kernel<<<NW4 / 256, 256>>>(Wk, wkh, wkl, NW4);
    split_kernel<<<NW4 / 256, 256>>>(Wv, wvh, wvl, NW4);
    split_kernel<<<NW4 / 256, 256>>>(Wo, woh, wol, NW4);

    // fused QKV (blockIdx.z selects weight/out)
    gemm_mma<false><<<dim3(H_ / 128, BS_ / 128, 3), 256>>>(
        xh, xl, wqh, wql, wkh, wkl, wvh, wvl, bq, bk, bv, q, k, v, nullptr);

    const int SC_SMEM = (64 + 64 + 127) * 65 * 4;  // 66300 B
    cudaFuncSetAttribute(scores_kernel, cudaFuncAttributeMaxDynamicSharedMemorySize, SC_SMEM);
    scores_kernel<<<dim3(16, 16, 64), 256, SC_SMEM>>>(q, k, de, mask, sc);

    softmax_kernel<<<BH_ * S_, 256>>>(sc);

    ctx_kernel<<<dim3(16, 64), 256>>>(sc, v, ctx);

    split_kernel<<<NX4 / 256, 256>>>(ctx, ch, cl, NX4);

    // out-proj with bias + residual
    gemm_mma<true><<<dim3(H_ / 128, BS_ / 128, 1), 256>>>(
        ch, cl, woh, wol, woh, wol, woh, wol, bo, bo, bo, y, y, y, x);

    ln_kernel<<<BS_, 256>>>(y, lng, lnb, out);
}

// round 4
// speedup vs baseline: 1.6517x; 1.6517x over previous
#include <cuda_runtime.h>
#include <cuda_bf16.h>
#include <cstdint>

#define S_   1024
#define H_   1024
#define B_   4
#define NH_  16
#define D_   64
#define BS_  4096
#define BH_  64

// ---------------- scratch (no allocs allowed) ----------------
__device__ float g_q[BS_ * H_];
__device__ float g_k[BS_ * H_];
__device__ float g_v[BS_ * H_];
__device__ float g_sc[(size_t)BH_ * S_ * S_];   // 256 MB scores/probs
__device__ float g_ctx[BS_ * H_];
__device__ float g_y[BS_ * H_];

// bf16 split buffers
__device__ __nv_bfloat16 g_xh[BS_ * H_], g_xl[BS_ * H_];
__device__ __nv_bfloat16 g_wqh[H_ * H_], g_wql[H_ * H_];
__device__ __nv_bfloat16 g_wkh[H_ * H_], g_wkl[H_ * H_];
__device__ __nv_bfloat16 g_wvh[H_ * H_], g_wvl[H_ * H_];
__device__ __nv_bfloat16 g_woh[H_ * H_], g_wol[H_ * H_];
__device__ __nv_bfloat16 g_ch[BS_ * H_], g_cl[BS_ * H_];

// ---------------- helpers -------------------------------------------------------
__device__ __forceinline__ uint32_t smem_u32(const void* p)
{
    return (uint32_t)__cvta_generic_to_shared(p);
}
__device__ __forceinline__ void ldm4(uint32_t* r, uint32_t addr)
{
    asm volatile("ldmatrix.sync.aligned.m8n8.x4.shared.b16 {%0,%1,%2,%3}, [%4];"
                 : "=r"(r[0]), "=r"(r[1]), "=r"(r[2]), "=r"(r[3]) : "r"(addr));
}
__device__ __forceinline__ void mma16816(float* c, const uint32_t* a, const uint32_t* b)
{
    asm volatile("mma.sync.aligned.m16n8k16.row.col.f32.bf16.bf16.f32 "
                 "{%0,%1,%2,%3}, {%4,%5,%6,%7}, {%8,%9}, {%0,%1,%2,%3};"
                 : "+f"(c[0]), "+f"(c[1]), "+f"(c[2]), "+f"(c[3])
                 : "r"(a[0]), "r"(a[1]), "r"(a[2]), "r"(a[3]), "r"(b[0]), "r"(b[1]));
}
__device__ __forceinline__ void cpa16(uint32_t dst, const void* src)
{
    asm volatile("cp.async.cg.shared.global [%0], [%1], 16;" :: "r"(dst), "l"(src));
}
#define CP_COMMIT() asm volatile("cp.async.commit_group;" ::: "memory")
#define CP_WAIT2()  asm volatile("cp.async.wait_group 2;" ::: "memory")
#define CP_WAIT1()  asm volatile("cp.async.wait_group 1;" ::: "memory")
#define CP_WAIT0()  asm volatile("cp.async.wait_group 0;" ::: "memory")

// ---------------- fp32 -> (hi,lo) bf16 split ---------------------------------------
__global__ void __launch_bounds__(256) split_kernel(const float* __restrict__ in,
                                                    __nv_bfloat16* __restrict__ hi,
                                                    __nv_bfloat16* __restrict__ lo,
                                                    int n4)
{
    int i = blockIdx.x * 256 + threadIdx.x;
    if (i >= n4) return;
    float4 a = ((const float4*)in)[i];
    __nv_bfloat16 h0 = __float2bfloat16(a.x);
    __nv_bfloat16 h1 = __float2bfloat16(a.y);
    __nv_bfloat16 h2 = __float2bfloat16(a.z);
    __nv_bfloat16 h3 = __float2bfloat16(a.w);
    __nv_bfloat162 hh0; hh0.x = h0; hh0.y = h1;
    __nv_bfloat162 hh1; hh1.x = h2; hh1.y = h3;
    ((__nv_bfloat162*)hi)[i * 2 + 0] = hh0;
    ((__nv_bfloat162*)hi)[i * 2 + 1] = hh1;
    __nv_bfloat162 ll0, ll1;
    ll0.x = __float2bfloat16(a.x - __bfloat162float(h0));
    ll0.y = __float2bfloat16(a.y - __bfloat162float(h1));
    ll1.x = __float2bfloat16(a.z - __bfloat162float(h2));
    ll1.y = __float2bfloat16(a.w - __bfloat162float(h3));
    ((__nv_bfloat162*)lo)[i * 2 + 0] = ll0;
    ((__nv_bfloat162*)lo)[i * 2 + 1] = ll1;
}

// 4 weight matrices in one launch (z selects)
__global__ void __launch_bounds__(256) split4_kernel(
    const float* __restrict__ w0, const float* __restrict__ w1,
    const float* __restrict__ w2, const float* __restrict__ w3,
    __nv_bfloat16* __restrict__ h0, __nv_bfloat16* __restrict__ l0p,
    __nv_bfloat16* __restrict__ h1, __nv_bfloat16* __restrict__ l1p,
    __nv_bfloat16* __restrict__ h2, __nv_bfloat16* __restrict__ l2p,
    __nv_bfloat16* __restrict__ h3, __nv_bfloat16* __restrict__ l3p)
{
    const int z = blockIdx.y;
    const float* in = (z == 0) ? w0 : (z == 1) ? w1 : (z == 2) ? w2 : w3;
    __nv_bfloat16* hi = (z == 0) ? h0 : (z == 1) ? h1 : (z == 2) ? h2 : h3;
    __nv_bfloat16* lo = (z == 0) ? l0p : (z == 1) ? l1p : (z == 2) ? l2p : l3p;
    int i = blockIdx.x * 256 + threadIdx.x;
    float4 a = ((const float4*)in)[i];
    __nv_bfloat16 a0 = __float2bfloat16(a.x);
    __nv_bfloat16 a1 = __float2bfloat16(a.y);
    __nv_bfloat16 a2 = __float2bfloat16(a.z);
    __nv_bfloat16 a3 = __float2bfloat16(a.w);
    __nv_bfloat162 hh0; hh0.x = a0; hh0.y = a1;
    __nv_bfloat162 hh1; hh1.x = a2; hh1.y = a3;
    ((__nv_bfloat162*)hi)[i * 2 + 0] = hh0;
    ((__nv_bfloat162*)hi)[i * 2 + 1] = hh1;
    __nv_bfloat162 ll0, ll1;
    ll0.x = __float2bfloat16(a.x - __bfloat162float(a0));
    ll0.y = __float2bfloat16(a.y - __bfloat162float(a1));
    ll1.x = __float2bfloat16(a.z - __bfloat162float(a2));
    ll1.y = __float2bfloat16(a.w - __bfloat162float(a3));
    ((__nv_bfloat162*)lo)[i * 2 + 0] = ll0;
    ((__nv_bfloat162*)lo)[i * 2 + 1] = ll1;
}

// ---------------- split-bf16 GEMM NT via HMMA, 3-stage cp.async pipeline -----------
// C[i,j] = sum_k A[i,k]*B[j,k] + bias[j] (+resid). M=4096, N=K=1024.
// block 128x128, 8 warps (2x4), warp 64x32, 3 mma passes (hh, hl, lh).
#define KT    32
#define LDS_  40                   // halves per row (32 + 8 pad); 80 B stride
#define MAT_B (128 * LDS_ * 2)     // 10240 B per matrix
#define STG_B (4 * MAT_B)          // 40960 B per stage
#define NSTG  3
#define GSM_TOTAL (NSTG * STG_B)   // 122880 B

template <bool RESID>
__global__ void __launch_bounds__(256) gemm_mma2(
    const __nv_bfloat16* __restrict__ Ah, const __nv_bfloat16* __restrict__ Al,
    const __nv_bfloat16* __restrict__ Bh0, const __nv_bfloat16* __restrict__ Bl0,
    const __nv_bfloat16* __restrict__ Bh1, const __nv_bfloat16* __restrict__ Bl1,
    const __nv_bfloat16* __restrict__ Bh2, const __nv_bfloat16* __restrict__ Bl2,
    const float* __restrict__ bias0, const float* __restrict__ bias1,
    const float* __restrict__ bias2,
    float* __restrict__ O0, float* __restrict__ O1, float* __restrict__ O2,
    const float* __restrict__ resid)
{
    extern __shared__ char smem[];
    const uint32_t sb = smem_u32(smem);

    const int z = blockIdx.z;
    const __nv_bfloat16* Bh = (z == 0) ? Bh0 : (z == 1) ? Bh1 : Bh2;
    const __nv_bfloat16* Bl = (z == 0) ? Bl0 : (z == 1) ? Bl1 : Bl2;
    const float* bias = (z == 0) ? bias0 : (z == 1) ? bias1 : bias2;
    float* O = (z == 0) ? O0 : (z == 1) ? O1 : O2;

    const int tid = threadIdx.x;
    const int lane = tid & 31, wid = tid >> 5;
    const int wm = wid >> 2, wn = wid & 3;
    const int bM = blockIdx.y * 128, bN = blockIdx.x * 128;

    float acc[4][4][4] = {};

    // cp.async mapping: 2 vec16 per thread per matrix
    const int v0row = tid >> 2, v0c = (tid & 3);            // vec idx tid
    const int v1row = (tid + 256) >> 2, v1c = ((tid + 256) & 3);

    const int NK = H_ / KT;  // 32

    // fragment addressing (validated in R2)
    const int q8 = lane >> 3, r8 = lane & 7;
    const int arowL = wm * 64 + (q8 & 1) * 8 + r8;
    const int browL = wn * 32 + (q8 >> 1) * 8 + r8;
    const int acolL = (q8 >> 1) * 8;
    const int bcolL = (q8 & 1) * 8;

    auto issue = [&](int kt) {
        const int st = kt % NSTG;
        const uint32_t base = sb + st * STG_B;
        const int k0 = kt * KT;
        const uint32_t d0 = (uint32_t)(v0row * (LDS_ * 2) + v0c * 16);
        const uint32_t d1 = (uint32_t)(v1row * (LDS_ * 2) + v1c * 16);
        const size_t gA0 = (size_t)(bM + v0row) * H_ + k0 + v0c * 8;
        const size_t gA1 = (size_t)(bM + v1row) * H_ + k0 + v1c * 8;
        const size_t gB0 = (size_t)(bN + v0row) * H_ + k0 + v0c * 8;
        const size_t gB1 = (size_t)(bN + v1row) * H_ + k0 + v1c * 8;
        cpa16(base + 0 * MAT_B + d0, Ah + gA0);
        cpa16(base + 0 * MAT_B + d1, Ah + gA1);
        cpa16(base + 1 * MAT_B + d0, Al + gA0);
        cpa16(base + 1 * MAT_B + d1, Al + gA1);
        cpa16(base + 2 * MAT_B + d0, Bh + gB0);
        cpa16(base + 2 * MAT_B + d1, Bh + gB1);
        cpa16(base + 3 * MAT_B + d0, Bl + gB0);
        cpa16(base + 3 * MAT_B + d1, Bl + gB1);
    };

    issue(0); CP_COMMIT();
    issue(1); CP_COMMIT();

    for (int kt = 0; kt < NK; kt++) {
        if (kt + 2 < NK) { issue(kt + 2); CP_COMMIT(); CP_WAIT2(); }
        else if (kt + 1 < NK) { CP_WAIT1(); }
        else { CP_WAIT0(); }
        __syncthreads();

        const int st = kt % NSTG;
        const uint32_t bAh = sb + st * STG_B + 0 * MAT_B;
        const uint32_t bAl = sb + st * STG_B + 1 * MAT_B;
        const uint32_t bBh = sb + st * STG_B + 2 * MAT_B;
        const uint32_t bBl = sb + st * STG_B + 3 * MAT_B;

#pragma unroll
        for (int ks = 0; ks < KT; ks += 16) {
            uint32_t afh[4][4], afl[4][4];
#pragma unroll
            for (int mt = 0; mt < 4; mt++) {
                const uint32_t ro = (uint32_t)(((arowL + mt * 16) * LDS_ + acolL + ks) * 2);
                ldm4(afh[mt], bAh + ro);
                ldm4(afl[mt], bAl + ro);
            }
            uint32_t bfh[2][4], bfl[2][4];
#pragma unroll
            for (int p = 0; p < 2; p++) {
                const uint32_t ro = (uint32_t)(((browL + p * 16) * LDS_ + bcolL + ks) * 2);
                ldm4(bfh[p], bBh + ro);
                ldm4(bfl[p], bBl + ro);
            }
#pragma unroll
            for (int mt = 0; mt < 4; mt++)
#pragma unroll
                for (int nt = 0; nt < 4; nt++) {
                    const uint32_t* bhp = &bfh[nt >> 1][(nt & 1) * 2];
                    const uint32_t* blp = &bfl[nt >> 1][(nt & 1) * 2];
                    mma16816(acc[mt][nt], afh[mt], bhp);
                    mma16816(acc[mt][nt], afh[mt], blp);
                    mma16816(acc[mt][nt], afl[mt], bhp);
                }
        }
        __syncthreads();
    }

    const int crow0 = bM + wm * 64 + (lane >> 2);
    const int ccol0 = bN + wn * 32 + (lane & 3) * 2;
#pragma unroll
    for (int mt = 0; mt < 4; mt++) {
        const int r0 = crow0 + mt * 16;
#pragma unroll
        for (int nt = 0; nt < 4; nt++) {
            const int c0 = ccol0 + nt * 8;
            float f0 = acc[mt][nt][0] + bias[c0];
            float f1 = acc[mt][nt][1] + bias[c0 + 1];
            float f2 = acc[mt][nt][2] + bias[c0];
            float f3 = acc[mt][nt][3] + bias[c0 + 1];
            if (RESID) {
                f0 += resid[(size_t)r0 * H_ + c0];
                f1 += resid[(size_t)r0 * H_ + c0 + 1];
                f2 += resid[(size_t)(r0 + 8) * H_ + c0];
                f3 += resid[(size_t)(r0 + 8) * H_ + c0 + 1];
            }
            O[(size_t)r0 * H_ + c0]           = f0;
            O[(size_t)r0 * H_ + c0 + 1]       = f1;
            O[(size_t)(r0 + 8) * H_ + c0]     = f2;
            O[(size_t)(r0 + 8) * H_ + c0 + 1] = f3;
        }
    }
}

// ---------------- scores: qk^T + (q+k)·dist_emb[l-r+1023], scaled + mask ----------
__global__ void __launch_bounds__(256) scores_kernel(
    const float* __restrict__ q, const float* __restrict__ k,
    const float* __restrict__ dist, const float* __restrict__ mask,
    float* __restrict__ sc)
{
    extern __shared__ float sm[];
    float* sQ = sm;
    float* sK = sm + 64 * 65;
    float* sP = sm + 128 * 65;

    const int l0 = blockIdx.x * 64;
    const int r0 = blockIdx.y * 64;
    const int bh = blockIdx.z;
    const int b = bh >> 4, h = bh & 15;
    const int tid = threadIdx.x;

    for (int idx = tid; idx < 64 * 16; idx += 256) {
        const int row = idx >> 4, c = (idx & 15) * 4;
        float4 qa = *(const float4*)(q + (size_t)(b * S_ + l0 + row) * H_ + h * D_ + c);
        float4 ka = *(const float4*)(k + (size_t)(b * S_ + r0 + row) * H_ + h * D_ + c);
        sQ[row * 65 + c + 0] = qa.x; sQ[row * 65 + c + 1] = qa.y;
        sQ[row * 65 + c + 2] = qa.z; sQ[row * 65 + c + 3] = qa.w;
        sK[row * 65 + c + 0] = ka.x; sK[row * 65 + c + 1] = ka.y;
        sK[row * 65 + c + 2] = ka.z; sK[row * 65 + c + 3] = ka.w;
    }
    const int prow0 = l0 - r0 + 960;
    for (int idx = tid; idx < 127 * 16; idx += 256) {
        const int t = idx >> 4, c = (idx & 15) * 4;
        float4 pa = *(const float4*)(dist + (size_t)(prow0 + t) * D_ + c);
        sP[t * 65 + c + 0] = pa.x; sP[t * 65 + c + 1] = pa.y;
        sP[t * 65 + c + 2] = pa.z; sP[t * 65 + c + 3] = pa.w;
    }
    __syncthreads();

    const int ty = tid >> 4, tx = tid & 15;
    const int tb = ty - tx + 63;
    float acc[4][4] = {};

#pragma unroll 2
    for (int d = 0; d < 64; d++) {
        float qv[4], kv[4], pv[7];
#pragma unroll
        for (int m = 0; m < 4; m++) qv[m] = sQ[(ty + 16 * m) * 65 + d];
#pragma unroll
        for (int n = 0; n < 4; n++) kv[n] = sK[(tx + 16 * n) * 65 + d];
#pragma unroll
        for (int u = 0; u < 7; u++) pv[u] = sP[(tb + 16 * (u - 3)) * 65 + d];
#pragma unroll
        for (int m = 0; m < 4; m++)
#pragma unroll
            for (int n = 0; n < 4; n++) {
                acc[m][n] = fmaf(qv[m], kv[n], acc[m][n]);
                acc[m][n] = fmaf(qv[m] + kv[n], pv[m - n + 3], acc[m][n]);
            }
    }

#pragma unroll
    for (int m = 0; m < 4; m++) {
        const int l = l0 + ty + 16 * m;
#pragma unroll
        for (int n = 0; n < 4; n++) {
            const int r = r0 + tx + 16 * n;
            sc[((size_t)bh * S_ + l) * S_ + r] = acc[m][n] * 0.125f + mask[b * S_ + r];
        }
    }
}

// ---------------- softmax ------------------------------------------------------------
__global__ void __launch_bounds__(256) softmax_kernel(float* __restrict__ sc)
{
    __shared__ float sred[8];
    __shared__ float sbc;
    const size_t row = blockIdx.x;
    float* p = sc + row * S_;
    const int tid = threadIdx.x;
    const int lane = tid & 31, wid = tid >> 5;

    float4 v = ((const float4*)p)[tid];

    float m = fmaxf(fmaxf(v.x, v.y), fmaxf(v.z, v.w));
#pragma unroll
    for (int o = 16; o > 0; o >>= 1) m = fmaxf(m, __shfl_xor_sync(~0u, m, o));
    if (lane == 0) sred[wid] = m;
    __syncthreads();
    if (tid == 0) {
        float t = sred[0];
#pragma unroll
        for (int i = 1; i < 8; i++) t = fmaxf(t, sred[i]);
        sbc = t;
    }
    __syncthreads();
    const float bm = sbc;

    float e0 = __expf(v.x - bm), e1 = __expf(v.y - bm);
    float e2 = __expf(v.z - bm), e3 = __expf(v.w - bm);
    float s = e0 + e1 + e2 + e3;
#pragma unroll
    for (int o = 16; o > 0; o >>= 1) s += __shfl_xor_sync(~0u, s, o);
    if (lane == 0) sred[wid] = s;
    __syncthreads();
    if (tid == 0) {
        float t = 0.f;
#pragma unroll
        for (int i = 0; i < 8; i++) t += sred[i];
        sbc = t;
    }
    __syncthreads();
    const float inv = 1.f / sbc;

    v.x = e0 * inv; v.y = e1 * inv; v.z = e2 * inv; v.w = e3 * inv;
    ((float4*)p)[tid] = v;
}

// ---------------- ctx = probs @ V ---------------------------------------------------
__global__ void __launch_bounds__(256) ctx_kernel(const float* __restrict__ probs,
                                                  const float* __restrict__ v,
                                                  float* __restrict__ ctx)
{
    __shared__ float sPb[64 * 65];
    __shared__ float sV[64 * 65];
    const int l0 = blockIdx.x * 64;
    const int bh = blockIdx.y;
    const int b = bh >> 4, h = bh & 15;
    const int tid = threadIdx.x;
    const int ty = tid >> 4, tx = tid & 15;

    float acc[4][4] = {};

    for (int r0 = 0; r0 < S_; r0 += 64) {
        __syncthreads();
        for (int idx = tid; idx < 64 * 16; idx += 256) {
            const int row = idx >> 4, c = (idx & 15) * 4;
            float4 pa = *(const float4*)(probs + ((size_t)bh * S_ + l0 + row) * S_ + r0 + c);
            float4 va = *(const float4*)(v + (size_t)(b * S_ + r0 + row) * H_ + h * D_ + c);
            sPb[row * 65 + c + 0] = pa.x; sPb[row * 65 + c + 1] = pa.y;
            sPb[row * 65 + c + 2] = pa.z; sPb[row * 65 + c + 3] = pa.w;
            sV[row * 65 + c + 0] = va.x; sV[row * 65 + c + 1] = va.y;
            sV[row * 65 + c + 2] = va.z; sV[row * 65 + c + 3] = va.w;
        }
        __syncthreads();
#pragma unroll 4
        for (int rr = 0; rr < 64; rr++) {
            float pvv[4], vv[4];
#pragma unroll
            for (int m = 0; m < 4; m++) pvv[m] = sPb[(ty + 16 * m) * 65 + rr];
#pragma unroll
            for (int n = 0; n < 4; n++) vv[n] = sV[rr * 65 + tx + 16 * n];
#pragma unroll
            for (int m = 0; m < 4; m++)
#pragma unroll
                for (int n = 0; n < 4; n++)
                    acc[m][n] = fmaf(pvv[m], vv[n], acc[m][n]);
        }
    }

#pragma unroll
    for (int m = 0; m < 4; m++) {
        const int l = l0 + ty + 16 * m;
#pragma unroll
        for (int n = 0; n < 4; n++)
            ctx[(size_t)(b * S_ + l) * H_ + h * D_ + tx + 16 * n] = acc[m][n];
    }
}

// ---------------- LayerNorm ----------------------------------------------------------
__global__ void __launch_bounds__(256) ln_kernel(const float* __restrict__ y,
                                                 const float* __restrict__ g,
                                                 const float* __restrict__ bb,
                                                 float* __restrict__ out)
{
    __shared__ float sred[8];
    __shared__ float sbc;
    const size_t row = blockIdx.x;
    const int tid = threadIdx.x;
    const int lane = tid & 31, wid = tid >> 5;

    float4 v = ((const float4*)(y + row * H_))[tid];

    float s = v.x + v.y + v.z + v.w;
#pragma unroll
    for (int o = 16; o > 0; o >>= 1) s += __shfl_xor_sync(~0u, s, o);
    if (lane == 0) sred[wid] = s;
    __syncthreads();
    if (tid == 0) {
        float t = 0.f;
#pragma unroll
        for (int i = 0; i < 8; i++) t += sred[i];
        sbc = t;
    }
    __syncthreads();
    const float mu = sbc * (1.f / H_);

    float dx = v.x - mu, dy = v.y - mu, dz = v.z - mu, dw = v.w - mu;
    float qq = dx * dx + dy * dy + dz * dz + dw * dw;
#pragma unroll
    for (int o = 16; o > 0; o >>= 1) qq += __shfl_xor_sync(~0u, qq, o);
    if (lane == 0) sred[wid] = qq;
    __syncthreads();
    if (tid == 0) {
        float t = 0.f;
#pragma unroll
        for (int i = 0; i < 8; i++) t += sred[i];
        sbc = t;
    }
    __syncthreads();
    const float rstd = rsqrtf(sbc * (1.f / H_) + 1e-12f);

    float4 gg = ((const float4*)g)[tid];
    float4 bt = ((const float4*)bb)[tid];
    float4 o;
    o.x = dx * rstd * gg.x + bt.x;
    o.y = dy * rstd * gg.y + bt.y;
    o.z = dz * rstd * gg.z + bt.z;
    o.w = dw * rstd * gg.w + bt.w;
    ((float4*)(out + row * H_))[tid] = o;
}

// ---------------- launch -----------------------------------------------------------
extern "C" void kernel_launch(void* const* d_in, const int* in_sizes, int n_in,
                              void* d_out, int out_size)
{
    (void)in_sizes; (void)n_in; (void)out_size;
    const float* x    = (const float*)d_in[0];
    const float* mask = (const float*)d_in[1];
    const float* Wq   = (const float*)d_in[2];
    const float* bq   = (const float*)d_in[3];
    const float* Wk   = (const float*)d_in[4];
    const float* bk   = (const float*)d_in[5];
    const float* Wv   = (const float*)d_in[6];
    const float* bv   = (const float*)d_in[7];
    const float* de   = (const float*)d_in[8];
    const float* Wo   = (const float*)d_in[9];
    const float* bo   = (const float*)d_in[10];
    const float* lng  = (const float*)d_in[11];
    const float* lnb  = (const float*)d_in[12];
    float* out = (float*)d_out;

    float *q, *k, *v, *sc, *ctx, *y;
    cudaGetSymbolAddress((void**)&q,   g_q);
    cudaGetSymbolAddress((void**)&k,   g_k);
    cudaGetSymbolAddress((void**)&v,   g_v);
    cudaGetSymbolAddress((void**)&sc,  g_sc);
    cudaGetSymbolAddress((void**)&ctx, g_ctx);
    cudaGetSymbolAddress((void**)&y,   g_y);

    __nv_bfloat16 *xh, *xl, *wqh, *wql, *wkh, *wkl, *wvh, *wvl, *woh, *wol, *ch, *cl;
    cudaGetSymbolAddress((void**)&xh, g_xh);   cudaGetSymbolAddress((void**)&xl, g_xl);
    cudaGetSymbolAddress((void**)&wqh, g_wqh); cudaGetSymbolAddress((void**)&wql, g_wql);
    cudaGetSymbolAddress((void**)&wkh, g_wkh); cudaGetSymbolAddress((void**)&wkl, g_wkl);
    cudaGetSymbolAddress((void**)&wvh, g_wvh); cudaGetSymbolAddress((void**)&wvl, g_wvl);
    cudaGetSymbolAddress((void**)&woh, g_woh); cudaGetSymbolAddress((void**)&wol, g_wol);
    cudaGetSymbolAddress((void**)&ch, g_ch);   cudaGetSymbolAddress((void**)&cl, g_cl);

    cudaFuncSetAttribute(gemm_mma2<false>, cudaFuncAttributeMaxDynamicSharedMemorySize, GSM_TOTAL);
    cudaFuncSetAttribute(gemm_mma2<true>,  cudaFuncAttributeMaxDynamicSharedMemorySize, GSM_TOTAL);
    const int SC_SMEM = (64 + 64 + 127) * 65 * 4;
    cudaFuncSetAttribute(scores_kernel, cudaFuncAttributeMaxDynamicSharedMemorySize, SC_SMEM);

    const int NX4 = BS_ * H_ / 4;
    const int NW4 = H_ * H_ / 4;
    split_kernel<<<NX4 / 256, 256>>>(x, xh, xl, NX4);
    split4_kernel<<<dim3(NW4 / 256, 4), 256>>>(Wq, Wk, Wv, Wo,
                                               wqh, wql, wkh, wkl,
                                               wvh, wvl, woh, wol);

    gemm_mma2<false><<<dim3(H_ / 128, BS_ / 128, 3), 256, GSM_TOTAL>>>(
        xh, xl, wqh, wql, wkh, wkl, wvh, wvl, bq, bk, bv, q, k, v, nullptr);

    scores_kernel<<<dim3(16, 16, 64), 256, SC_SMEM>>>(q, k, de, mask, sc);

    softmax_kernel<<<BH_ * S_, 256>>>(sc);

    ctx_kernel<<<dim3(16, 64), 256>>>(sc, v, ctx);

    split_kernel<<<NX4 / 256, 256>>>(ctx, ch, cl, NX4);

    gemm_mma2<true><<<dim3(H_ / 128, BS_ / 128, 1), 256, GSM_TOTAL>>>(
        ch, cl, woh, wol, woh, wol, woh, wol, bo, bo, bo, y, y, y, x);

    ln_kernel<<<BS_, 256>>>(y, lng, lnb, out);
}

// round 6
// speedup vs baseline: 2.5641x; 1.5524x over previous
#include <cuda_runtime.h>
#include <cuda_bf16.h>
#include <cstdint>

#define S_   1024
#define H_   1024
#define B_   4
#define NH_  16
#define D_   64
#define BS_  4096
#define BH_  64

// ---------------- scratch (no allocs allowed) ----------------
__device__ float g_y[BS_ * H_];

__device__ __nv_bfloat16 g_xh[BS_ * H_], g_xl[BS_ * H_];
__device__ __nv_bfloat16 g_wqh[H_ * H_], g_wql[H_ * H_];
__device__ __nv_bfloat16 g_wkh[H_ * H_], g_wkl[H_ * H_];
__device__ __nv_bfloat16 g_wvh[H_ * H_], g_wvl[H_ * H_];
__device__ __nv_bfloat16 g_woh[H_ * H_], g_wol[H_ * H_];
__device__ __nv_bfloat16 g_qh[BS_ * H_], g_ql[BS_ * H_];
__device__ __nv_bfloat16 g_kh[BS_ * H_], g_kl[BS_ * H_];
__device__ __nv_bfloat16 g_vh[BS_ * H_], g_vl[BS_ * H_];
__device__ __nv_bfloat16 g_deh[2047 * 64], g_del[2047 * 64];
__device__ __nv_bfloat16 g_ch[BS_ * H_], g_cl[BS_ * H_];

// ---------------- helpers -------------------------------------------------------
__device__ __forceinline__ uint32_t smem_u32(const void* p)
{
    return (uint32_t)__cvta_generic_to_shared(p);
}
__device__ __forceinline__ void ldm4(uint32_t* r, uint32_t addr)
{
    asm volatile("ldmatrix.sync.aligned.m8n8.x4.shared.b16 {%0,%1,%2,%3}, [%4];"
                 : "=r"(r[0]), "=r"(r[1]), "=r"(r[2]), "=r"(r[3]) : "r"(addr));
}
__device__ __forceinline__ void ldm4t(uint32_t* r, uint32_t addr)
{
    asm volatile("ldmatrix.sync.aligned.m8n8.x4.trans.shared.b16 {%0,%1,%2,%3}, [%4];"
                 : "=r"(r[0]), "=r"(r[1]), "=r"(r[2]), "=r"(r[3]) : "r"(addr));
}
__device__ __forceinline__ void mma16816(float* c, const uint32_t* a, const uint32_t* b)
{
    asm volatile("mma.sync.aligned.m16n8k16.row.col.f32.bf16.bf16.f32 "
                 "{%0,%1,%2,%3}, {%4,%5,%6,%7}, {%8,%9}, {%0,%1,%2,%3};"
                 : "+f"(c[0]), "+f"(c[1]), "+f"(c[2]), "+f"(c[3])
                 : "r"(a[0]), "r"(a[1]), "r"(a[2]), "r"(a[3]), "r"(b[0]), "r"(b[1]));
}
__device__ __forceinline__ void cpa16(uint32_t dst, const void* src)
{
    asm volatile("cp.async.cg.shared.global [%0], [%1], 16;" :: "r"(dst), "l"(src));
}
#define CP_COMMIT() asm volatile("cp.async.commit_group;" ::: "memory")
#define CP_WAIT2()  asm volatile("cp.async.wait_group 2;" ::: "memory")
#define CP_WAIT1()  asm volatile("cp.async.wait_group 1;" ::: "memory")
#define CP_WAIT0()  asm volatile("cp.async.wait_group 0;" ::: "memory")

__device__ __forceinline__ void store_split2(__nv_bfloat16* Hp, __nv_bfloat16* Lp,
                                             size_t off, float f0, float f1)
{
    __nv_bfloat162 hp, lp;
    hp.x = __float2bfloat16(f0); hp.y = __float2bfloat16(f1);
    lp.x = __float2bfloat16(f0 - __bfloat162float(hp.x));
    lp.y = __float2bfloat16(f1 - __bfloat162float(hp.y));
    *(__nv_bfloat162*)(Hp + off) = hp;
    *(__nv_bfloat162*)(Lp + off) = lp;
}

// ---------------- fp32 -> (hi,lo) bf16 split ---------------------------------------
__global__ void __launch_bounds__(256) split_kernel(const float* __restrict__ in,
                                                    __nv_bfloat16* __restrict__ hi,
                                                    __nv_bfloat16* __restrict__ lo,
                                                    int n4)
{
    int i = blockIdx.x * 256 + threadIdx.x;
    if (i >= n4) return;
    float4 a = ((const float4*)in)[i];
    __nv_bfloat16 h0 = __float2bfloat16(a.x);
    __nv_bfloat16 h1 = __float2bfloat16(a.y);
    __nv_bfloat16 h2 = __float2bfloat16(a.z);
    __nv_bfloat16 h3 = __float2bfloat16(a.w);
    __nv_bfloat162 hh0; hh0.x = h0; hh0.y = h1;
    __nv_bfloat162 hh1; hh1.x = h2; hh1.y = h3;
    ((__nv_bfloat162*)hi)[i * 2 + 0] = hh0;
    ((__nv_bfloat162*)hi)[i * 2 + 1] = hh1;
    __nv_bfloat162 ll0, ll1;
    ll0.x = __float2bfloat16(a.x - __bfloat162float(h0));
    ll0.y = __float2bfloat16(a.y - __bfloat162float(h1));
    ll1.x = __float2bfloat16(a.z - __bfloat162float(h2));
    ll1.y = __float2bfloat16(a.w - __bfloat162float(h3));
    ((__nv_bfloat162*)lo)[i * 2 + 0] = ll0;
    ((__nv_bfloat162*)lo)[i * 2 + 1] = ll1;
}

__global__ void __launch_bounds__(256) split4_kernel(
    const float* __restrict__ w0, const float* __restrict__ w1,
    const float* __restrict__ w2, const float* __restrict__ w3,
    __nv_bfloat16* __restrict__ h0, __nv_bfloat16* __restrict__ l0p,
    __nv_bfloat16* __restrict__ h1, __nv_bfloat16* __restrict__ l1p,
    __nv_bfloat16* __restrict__ h2, __nv_bfloat16* __restrict__ l2p,
    __nv_bfloat16* __restrict__ h3, __nv_bfloat16* __restrict__ l3p)
{
    const int z = blockIdx.y;
    const float* in = (z == 0) ? w0 : (z == 1) ? w1 : (z == 2) ? w2 : w3;
    __nv_bfloat16* hi = (z == 0) ? h0 : (z == 1) ? h1 : (z == 2) ? h2 : h3;
    __nv_bfloat16* lo = (z == 0) ? l0p : (z == 1) ? l1p : (z == 2) ? l2p : l3p;
    int i = blockIdx.x * 256 + threadIdx.x;
    float4 a = ((const float4*)in)[i];
    __nv_bfloat16 a0 = __float2bfloat16(a.x);
    __nv_bfloat16 a1 = __float2bfloat16(a.y);
    __nv_bfloat16 a2 = __float2bfloat16(a.z);
    __nv_bfloat16 a3 = __float2bfloat16(a.w);
    __nv_bfloat162 hh0; hh0.x = a0; hh0.y = a1;
    __nv_bfloat162 hh1; hh1.x = a2; hh1.y = a3;
    ((__nv_bfloat162*)hi)[i * 2 + 0] = hh0;
    ((__nv_bfloat162*)hi)[i * 2 + 1] = hh1;
    __nv_bfloat162 ll0, ll1;
    ll0.x = __float2bfloat16(a.x - __bfloat162float(a0));
    ll0.y = __float2bfloat16(a.y - __bfloat162float(a1));
    ll1.x = __float2bfloat16(a.z - __bfloat162float(a2));
    ll1.y = __float2bfloat16(a.w - __bfloat162float(a3));
    ((__nv_bfloat162*)lo)[i * 2 + 0] = ll0;
    ((__nv_bfloat162*)lo)[i * 2 + 1] = ll1;
}

// ---------------- split-bf16 GEMM NT via HMMA, 3-stage cp.async pipeline -----------
// EPI: 0 = fp32+bias, 1 = fp32+bias+resid, 2 = split bf16 hi/lo +bias
#define KT    32
#define LDS_  40
#define MAT_B (128 * LDS_ * 2)
#define STG_B (4 * MAT_B)
#define NSTG  3
#define GSM_TOTAL (NSTG * STG_B)

template <int EPI>
__global__ void __launch_bounds__(256) gemm_mma2(
    const __nv_bfloat16* __restrict__ Ah, const __nv_bfloat16* __restrict__ Al,
    const __nv_bfloat16* __restrict__ Bh0, const __nv_bfloat16* __restrict__ Bl0,
    const __nv_bfloat16* __restrict__ Bh1, const __nv_bfloat16* __restrict__ Bl1,
    const __nv_bfloat16* __restrict__ Bh2, const __nv_bfloat16* __restrict__ Bl2,
    const float* __restrict__ bias0, const float* __restrict__ bias1,
    const float* __restrict__ bias2,
    void* O0, void* O1, void* O2,
    void* L0, void* L1, void* L2,
    const float* __restrict__ resid)
{
    extern __shared__ char smem[];
    const uint32_t sb = smem_u32(smem);

    const int z = blockIdx.z;
    const __nv_bfloat16* Bh = (z == 0) ? Bh0 : (z == 1) ? Bh1 : Bh2;
    const __nv_bfloat16* Bl = (z == 0) ? Bl0 : (z == 1) ? Bl1 : Bl2;
    const float* bias = (z == 0) ? bias0 : (z == 1) ? bias1 : bias2;
    void* Ov = (z == 0) ? O0 : (z == 1) ? O1 : O2;
    void* Lv = (z == 0) ? L0 : (z == 1) ? L1 : L2;

    const int tid = threadIdx.x;
    const int lane = tid & 31, wid = tid >> 5;
    const int wm = wid >> 2, wn = wid & 3;
    const int bM = blockIdx.y * 128, bN = blockIdx.x * 128;

    float acc[4][4][4] = {};

    const int v0row = tid >> 2, v0c = (tid & 3);
    const int v1row = (tid + 256) >> 2, v1c = ((tid + 256) & 3);
    const int NK = H_ / KT;

    const int q8 = lane >> 3, r8 = lane & 7;
    const int arowL = wm * 64 + (q8 & 1) * 8 + r8;
    const int browL = wn * 32 + (q8 >> 1) * 8 + r8;
    const int acolL = (q8 >> 1) * 8;
    const int bcolL = (q8 & 1) * 8;

    auto issue = [&](int kt) {
        const int st = kt % NSTG;
        const uint32_t base = sb + st * STG_B;
        const int k0 = kt * KT;
        const uint32_t d0 = (uint32_t)(v0row * (LDS_ * 2) + v0c * 16);
        const uint32_t d1 = (uint32_t)(v1row * (LDS_ * 2) + v1c * 16);
        const size_t gA0 = (size_t)(bM + v0row) * H_ + k0 + v0c * 8;
        const size_t gA1 = (size_t)(bM + v1row) * H_ + k0 + v1c * 8;
        const size_t gB0 = (size_t)(bN + v0row) * H_ + k0 + v0c * 8;
        const size_t gB1 = (size_t)(bN + v1row) * H_ + k0 + v1c * 8;
        cpa16(base + 0 * MAT_B + d0, Ah + gA0);
        cpa16(base + 0 * MAT_B + d1, Ah + gA1);
        cpa16(base + 1 * MAT_B + d0, Al + gA0);
        cpa16(base + 1 * MAT_B + d1, Al + gA1);
        cpa16(base + 2 * MAT_B + d0, Bh + gB0);
        cpa16(base + 2 * MAT_B + d1, Bh + gB1);
        cpa16(base + 3 * MAT_B + d0, Bl + gB0);
        cpa16(base + 3 * MAT_B + d1, Bl + gB1);
    };

    issue(0); CP_COMMIT();
    issue(1); CP_COMMIT();

    for (int kt = 0; kt < NK; kt++) {
        if (kt + 2 < NK) { issue(kt + 2); CP_COMMIT(); CP_WAIT2(); }
        else if (kt + 1 < NK) { CP_WAIT1(); }
        else { CP_WAIT0(); }
        __syncthreads();

        const int st = kt % NSTG;
        const uint32_t bAh = sb + st * STG_B + 0 * MAT_B;
        const uint32_t bAl = sb + st * STG_B + 1 * MAT_B;
        const uint32_t bBh = sb + st * STG_B + 2 * MAT_B;
        const uint32_t bBl = sb + st * STG_B + 3 * MAT_B;

#pragma unroll
        for (int ks = 0; ks < KT; ks += 16) {
            uint32_t afh[4][4], afl[4][4];
#pragma unroll
            for (int mt = 0; mt < 4; mt++) {
                const uint32_t ro = (uint32_t)(((arowL + mt * 16) * LDS_ + acolL + ks) * 2);
                ldm4(afh[mt], bAh + ro);
                ldm4(afl[mt], bAl + ro);
            }
            uint32_t bfh[2][4], bfl[2][4];
#pragma unroll
            for (int p = 0; p < 2; p++) {
                const uint32_t ro = (uint32_t)(((browL + p * 16) * LDS_ + bcolL + ks) * 2);
                ldm4(bfh[p], bBh + ro);
                ldm4(bfl[p], bBl + ro);
            }
#pragma unroll
            for (int mt = 0; mt < 4; mt++)
#pragma unroll
                for (int nt = 0; nt < 4; nt++) {
                    const uint32_t* bhp = &bfh[nt >> 1][(nt & 1) * 2];
                    const uint32_t* blp = &bfl[nt >> 1][(nt & 1) * 2];
                    mma16816(acc[mt][nt], afh[mt], bhp);
                    mma16816(acc[mt][nt], afh[mt], blp);
                    mma16816(acc[mt][nt], afl[mt], bhp);
                }
        }
        __syncthreads();
    }

    const int crow0 = bM + wm * 64 + (lane >> 2);
    const int ccol0 = bN + wn * 32 + (lane & 3) * 2;
#pragma unroll
    for (int mt = 0; mt < 4; mt++) {
        const int r0 = crow0 + mt * 16;
#pragma unroll
        for (int nt = 0; nt < 4; nt++) {
            const int c0 = ccol0 + nt * 8;
            float f0 = acc[mt][nt][0] + bias[c0];
            float f1 = acc[mt][nt][1] + bias[c0 + 1];
            float f2 = acc[mt][nt][2] + bias[c0];
            float f3 = acc[mt][nt][3] + bias[c0 + 1];
            if (EPI == 1) {
                f0 += resid[(size_t)r0 * H_ + c0];
                f1 += resid[(size_t)r0 * H_ + c0 + 1];
                f2 += resid[(size_t)(r0 + 8) * H_ + c0];
                f3 += resid[(size_t)(r0 + 8) * H_ + c0 + 1];
            }
            if (EPI == 2) {
                __nv_bfloat16* OH = (__nv_bfloat16*)Ov;
                __nv_bfloat16* OL = (__nv_bfloat16*)Lv;
                store_split2(OH, OL, (size_t)r0 * H_ + c0, f0, f1);
                store_split2(OH, OL, (size_t)(r0 + 8) * H_ + c0, f2, f3);
            } else {
                float* O = (float*)Ov;
                O[(size_t)r0 * H_ + c0]           = f0;
                O[(size_t)r0 * H_ + c0 + 1]       = f1;
                O[(size_t)(r0 + 8) * H_ + c0]     = f2;
                O[(size_t)(r0 + 8) * H_ + c0 + 1] = f3;
            }
        }
    }
}

// ---------------- fused flash attention with relative_key_query bias ---------------
#define FQ    0
#define FK    18432
#define FV    36864       // 2 bufs x (h 9216 + l 9216)
#define FP    73728       // h 18432, l 18432 (128 rows x 72 pitch)
#define FS2   110592      // fp32 [64][132]; probs hi/lo overlap here (2x9216)
#define FS3   144384
#define FRED  178176      // redm [2][64] f32, redsum [2][64] f32
#define FMASK 179200      // 1024 f32
#define FSM_TOTAL 183296

__global__ void __launch_bounds__(256) fused_attn(
    const __nv_bfloat16* __restrict__ qh, const __nv_bfloat16* __restrict__ ql,
    const __nv_bfloat16* __restrict__ kh, const __nv_bfloat16* __restrict__ kl,
    const __nv_bfloat16* __restrict__ vh, const __nv_bfloat16* __restrict__ vl,
    const __nv_bfloat16* __restrict__ deh, const __nv_bfloat16* __restrict__ del,
    const float* __restrict__ mask,
    __nv_bfloat16* __restrict__ ch, __nv_bfloat16* __restrict__ cl)
{
    extern __shared__ char smem[];
    const uint32_t sb = smem_u32(smem);
    const int tid = threadIdx.x, lane = tid & 31, wid = tid >> 5;
    const int wr = wid >> 1, wc = wid & 1;
    const int l0 = blockIdx.x * 64;
    const int bh = blockIdx.y;
    const int b = bh >> 4, h = bh & 15;
    const int hcol = h * D_;

    const int q8 = lane >> 3, r8 = lane & 7;
    const int aRow = (q8 & 1) * 8 + r8, aCol = (q8 >> 1) * 8;
    const int bRow = (q8 >> 1) * 8 + r8, bCol = (q8 & 1) * 8;

    auto cp_t64 = [&](uint32_t dstbase, const __nv_bfloat16* srcH,
                      const __nv_bfloat16* srcL, int growbase) {
#pragma unroll
        for (int j = 0; j < 2; j++) {
            int v = tid + 256 * j;
            int row = v >> 3, c = v & 7;
            uint32_t d = dstbase + (uint32_t)(row * 72 + c * 8) * 2;
            cpa16(d, srcH + (size_t)(growbase + row) * H_ + hcol + c * 8);
            cpa16(d + 9216, srcL + (size_t)(growbase + row) * H_ + hcol + c * 8);
        }
    };
    auto cp_P = [&](int it) {
        const int prow0 = l0 - it * 64 + 960;
#pragma unroll
        for (int j = 0; j < 4; j++) {
            int v = tid + 256 * j;
            int row = v >> 3, c = v & 7;
            uint32_t off = (uint32_t)(row * 72 + c * 8) * 2;
            if (row < 127) {
                cpa16(sb + FP + off, deh + (size_t)(prow0 + row) * 64 + c * 8);
                cpa16(sb + FP + 18432 + off, del + (size_t)(prow0 + row) * 64 + c * 8);
            } else {
                uint4 zz = {0, 0, 0, 0};
                *(uint4*)(smem + FP + off) = zz;
                *(uint4*)(smem + FP + 18432 + off) = zz;
            }
        }
    };

    // ---- initial loads: Q, K(0), V(0)->buf0, P(0), full mask row ----
    cp_t64(sb + FQ, qh, ql, b * S_ + l0);
    cp_t64(sb + FK, kh, kl, b * S_ + 0);
    cp_t64(sb + FV, vh, vl, b * S_ + 0);
    cp_P(0);
    cpa16(sb + FMASK + tid * 16, mask + (size_t)b * S_ + tid * 4);   // 256 x 16B = full 1024 floats
    CP_COMMIT();

    float O[4][4] = {};
    float mrunA = -1e30f, mrunB = -1e30f;
    float srunA = 0.f, srunB = 0.f;

    const int la = wr * 16 + (lane >> 2);
    float* S2p = (float*)(smem + FS2);
    float* S3p = (float*)(smem + FS3);
    float* redm = (float*)(smem + FRED);
    float* redsum = (float*)(smem + FRED + 512);
    const float* maskS = (const float*)(smem + FMASK);

    CP_WAIT0();
    __syncthreads();

    for (int it = 0; it < 16; it++) {
        if (it > 0) { CP_WAIT0(); __syncthreads(); }
        const uint32_t Vb = sb + FV + (uint32_t)(it & 1) * 18432;

        // ---- S1 = Q @ K^T (16l x 32r per warp), 3-pass ----
        float accS[4][4] = {};
#pragma unroll
        for (int ks = 0; ks < 4; ks++) {
            uint32_t ah_[4], al_[4];
            ldm4(ah_, sb + FQ + (uint32_t)(((wr * 16 + aRow) * 72) + ks * 16 + aCol) * 2);
            ldm4(al_, sb + FQ + 9216 + (uint32_t)(((wr * 16 + aRow) * 72) + ks * 16 + aCol) * 2);
            uint32_t kbh[2][4], kbl[2][4];
#pragma unroll
            for (int p = 0; p < 2; p++) {
                uint32_t ro = (uint32_t)(((wc * 32 + p * 16 + bRow) * 72) + ks * 16 + bCol) * 2;
                ldm4(kbh[p], sb + FK + ro);
                ldm4(kbl[p], sb + FK + 9216 + ro);
            }
#pragma unroll
            for (int nf = 0; nf < 4; nf++) {
                const uint32_t* bhp = &kbh[nf >> 1][(nf & 1) * 2];
                const uint32_t* blp = &kbl[nf >> 1][(nf & 1) * 2];
                mma16816(accS[nf], ah_, bhp);
                mma16816(accS[nf], ah_, blp);
                mma16816(accS[nf], al_, bhp);
            }
        }

        // ---- S2 = Q @ P^T  (64l x 16t per warp) -> stage ----
        {
            float a2[4][2][4] = {};
#pragma unroll
            for (int ks = 0; ks < 4; ks++) {
                uint32_t pbh[4], pbl[4];
                uint32_t ro = (uint32_t)(((wid * 16 + bRow) * 72) + ks * 16 + bCol) * 2;
                ldm4(pbh, sb + FP + ro);
                ldm4(pbl, sb + FP + 18432 + ro);
#pragma unroll
                for (int mt = 0; mt < 4; mt++) {
                    uint32_t ah_[4], al_[4];
                    uint32_t ra = (uint32_t)(((mt * 16 + aRow) * 72) + ks * 16 + aCol) * 2;
                    ldm4(ah_, sb + FQ + ra);
                    ldm4(al_, sb + FQ + 9216 + ra);
#pragma unroll
                    for (int nf = 0; nf < 2; nf++) {
                        const uint32_t* bhp = &pbh[nf * 2];
                        const uint32_t* blp = &pbl[nf * 2];
                        mma16816(a2[mt][nf], ah_, bhp);
                        mma16816(a2[mt][nf], ah_, blp);
                        mma16816(a2[mt][nf], al_, bhp);
                    }
                }
            }
#pragma unroll
            for (int mt = 0; mt < 4; mt++) {
                const int rr = mt * 16 + (lane >> 2);
#pragma unroll
                for (int nf = 0; nf < 2; nf++) {
                    const int cc = wid * 16 + nf * 8 + (lane & 3) * 2;
                    float2 u0; u0.x = a2[mt][nf][0]; u0.y = a2[mt][nf][1];
                    float2 u1; u1.x = a2[mt][nf][2]; u1.y = a2[mt][nf][3];
                    *(float2*)&S2p[rr * 132 + cc] = u0;
                    *(float2*)&S2p[(rr + 8) * 132 + cc] = u1;
                }
            }
        }
        // ---- S3 = K @ P^T -> stage ----
        {
            float a3[4][2][4] = {};
#pragma unroll
            for (int ks = 0; ks < 4; ks++) {
                uint32_t pbh[4], pbl[4];
                uint32_t ro = (uint32_t)(((wid * 16 + bRow) * 72) + ks * 16 + bCol) * 2;
                ldm4(pbh, sb + FP + ro);
                ldm4(pbl, sb + FP + 18432 + ro);
#pragma unroll
                for (int mt = 0; mt < 4; mt++) {
                    uint32_t ah_[4], al_[4];
                    uint32_t ra = (uint32_t)(((mt * 16 + aRow) * 72) + ks * 16 + aCol) * 2;
                    ldm4(ah_, sb + FK + ra);
                    ldm4(al_, sb + FK + 9216 + ra);
#pragma unroll
                    for (int nf = 0; nf < 2; nf++) {
                        const uint32_t* bhp = &pbh[nf * 2];
                        const uint32_t* blp = &pbl[nf * 2];
                        mma16816(a3[mt][nf], ah_, bhp);
                        mma16816(a3[mt][nf], ah_, blp);
                        mma16816(a3[mt][nf], al_, bhp);
                    }
                }
            }
#pragma unroll
            for (int mt = 0; mt < 4; mt++) {
                const int rr = mt * 16 + (lane >> 2);
#pragma unroll
                for (int nf = 0; nf < 2; nf++) {
                    const int cc = wid * 16 + nf * 8 + (lane & 3) * 2;
                    float2 u0; u0.x = a3[mt][nf][0]; u0.y = a3[mt][nf][1];
                    float2 u1; u1.x = a3[mt][nf][2]; u1.y = a3[mt][nf][3];
                    *(float2*)&S3p[rr * 132 + cc] = u0;
                    *(float2*)&S3p[(rr + 8) * 132 + cc] = u1;
                }
            }
        }
        __syncthreads();   // staging visible; K,P reads done

        // prefetch next K,P,V
        if (it < 15) {
            cp_t64(sb + FK, kh, kl, b * S_ + (it + 1) * 64);
            cp_P(it + 1);
            cp_t64(sb + FV + (uint32_t)((it + 1) & 1) * 18432, vh, vl, b * S_ + (it + 1) * 64);
            CP_COMMIT();
        }

        // ---- gather + mask + scale ----
        float s[4][4];
#pragma unroll
        for (int nf = 0; nf < 4; nf++) {
            const int c0 = wc * 32 + nf * 8 + (lane & 3) * 2;
            const int t0 = la - c0 + 63;
            const float mk0 = maskS[it * 64 + c0];
            const float mk1 = maskS[it * 64 + c0 + 1];
            s[nf][0] = (accS[nf][0] + S2p[la * 132 + t0]           + S3p[c0 * 132 + t0])           * 0.125f + mk0;
            s[nf][1] = (accS[nf][1] + S2p[la * 132 + t0 - 1]       + S3p[(c0 + 1) * 132 + t0 - 1]) * 0.125f + mk1;
            s[nf][2] = (accS[nf][2] + S2p[(la + 8) * 132 + t0 + 8] + S3p[c0 * 132 + t0 + 8])       * 0.125f + mk0;
            s[nf][3] = (accS[nf][3] + S2p[(la + 8) * 132 + t0 + 7] + S3p[(c0 + 1) * 132 + t0 + 7]) * 0.125f + mk1;
        }

        // ---- online softmax: row max ----
        float mA = -1e30f, mB = -1e30f;
#pragma unroll
        for (int nf = 0; nf < 4; nf++) {
            mA = fmaxf(mA, fmaxf(s[nf][0], s[nf][1]));
            mB = fmaxf(mB, fmaxf(s[nf][2], s[nf][3]));
        }
        mA = fmaxf(mA, __shfl_xor_sync(~0u, mA, 1));
        mA = fmaxf(mA, __shfl_xor_sync(~0u, mA, 2));
        mB = fmaxf(mB, __shfl_xor_sync(~0u, mB, 1));
        mB = fmaxf(mB, __shfl_xor_sync(~0u, mB, 2));
        if ((lane & 3) == 0) {
            redm[wc * 64 + la] = mA;
            redm[wc * 64 + la + 8] = mB;
        }
        __syncthreads();

        mA = fmaxf(mA, redm[(wc ^ 1) * 64 + la]);
        mB = fmaxf(mB, redm[(wc ^ 1) * 64 + la + 8]);
        const float mnA = fmaxf(mrunA, mA), mnB = fmaxf(mrunB, mB);
        const float sclA = __expf(mrunA - mnA), sclB = __expf(mrunB - mnB);
        mrunA = mnA; mrunB = mnB;
#pragma unroll
        for (int nf = 0; nf < 4; nf++) {
            O[nf][0] *= sclA; O[nf][1] *= sclA;
            O[nf][2] *= sclB; O[nf][3] *= sclB;
        }

        __nv_bfloat16* PsH = (__nv_bfloat16*)(smem + FS2);
        __nv_bfloat16* PsL = (__nv_bfloat16*)(smem + FS2 + 9216);
        float suA = 0.f, suB = 0.f;
#pragma unroll
        for (int nf = 0; nf < 4; nf++) {
            const int c0 = wc * 32 + nf * 8 + (lane & 3) * 2;
            float e0 = __expf(s[nf][0] - mnA), e1 = __expf(s[nf][1] - mnA);
            float e2 = __expf(s[nf][2] - mnB), e3 = __expf(s[nf][3] - mnB);
            suA += e0 + e1; suB += e2 + e3;
            store_split2(PsH, PsL, (size_t)la * 72 + c0, e0, e1);
            store_split2(PsH, PsL, (size_t)(la + 8) * 72 + c0, e2, e3);
        }
        suA += __shfl_xor_sync(~0u, suA, 1);
        suA += __shfl_xor_sync(~0u, suA, 2);
        suB += __shfl_xor_sync(~0u, suB, 1);
        suB += __shfl_xor_sync(~0u, suB, 2);
        if ((lane & 3) == 0) {
            redsum[wc * 64 + la] = suA;
            redsum[wc * 64 + la + 8] = suB;
        }
        __syncthreads();

        suA += redsum[(wc ^ 1) * 64 + la];
        suB += redsum[(wc ^ 1) * 64 + la + 8];
        srunA = srunA * sclA + suA;
        srunB = srunB * sclB + suB;

        // ---- O += P @ V (3-pass) ----
#pragma unroll
        for (int ks = 0; ks < 4; ks++) {
            uint32_t pah[4], pal[4];
            uint32_t ra = (uint32_t)(((wr * 16 + aRow) * 72) + ks * 16 + aCol) * 2;
            ldm4(pah, sb + FS2 + ra);
            ldm4(pal, sb + FS2 + 9216 + ra);
            uint32_t vbh[2][4], vbl[2][4];
#pragma unroll
            for (int p = 0; p < 2; p++) {
                uint32_t ro = (uint32_t)(((ks * 16 + aRow) * 72) + wc * 32 + p * 16 + aCol) * 2;
                ldm4t(vbh[p], Vb + ro);
                ldm4t(vbl[p], Vb + 9216 + ro);
            }
#pragma unroll
            for (int nf = 0; nf < 4; nf++) {
                const uint32_t* bhp = &vbh[nf >> 1][(nf & 1) * 2];
                const uint32_t* blp = &vbl[nf >> 1][(nf & 1) * 2];
                mma16816(O[nf], pah, bhp);
                mma16816(O[nf], pah, blp);
                mma16816(O[nf], pal, bhp);
            }
        }
        __syncthreads();
    }

    // ---- epilogue: ctx split hi/lo ----
    const float iA = 1.f / srunA, iB = 1.f / srunB;
#pragma unroll
    for (int nf = 0; nf < 4; nf++) {
        const int col = hcol + wc * 32 + nf * 8 + (lane & 3) * 2;
        const size_t rowA = (size_t)(b * S_ + l0 + la) * H_ + col;
        const size_t rowB = (size_t)(b * S_ + l0 + la + 8) * H_ + col;
        store_split2(ch, cl, rowA, O[nf][0] * iA, O[nf][1] * iA);
        store_split2(ch, cl, rowB, O[nf][2] * iB, O[nf][3] * iB);
    }
}

// ---------------- LayerNorm ----------------------------------------------------------
__global__ void __launch_bounds__(256) ln_kernel(const float* __restrict__ y,
                                                 const float* __restrict__ g,
                                                 const float* __restrict__ bb,
                                                 float* __restrict__ out)
{
    __shared__ float sred[8];
    __shared__ float sbc;
    const size_t row = blockIdx.x;
    const int tid = threadIdx.x;
    const int lane = tid & 31, wid = tid >> 5;

    float4 v = ((const float4*)(y + row * H_))[tid];

    float s = v.x + v.y + v.z + v.w;
#pragma unroll
    for (int o = 16; o > 0; o >>= 1) s += __shfl_xor_sync(~0u, s, o);
    if (lane == 0) sred[wid] = s;
    __syncthreads();
    if (tid == 0) {
        float t = 0.f;
#pragma unroll
        for (int i = 0; i < 8; i++) t += sred[i];
        sbc = t;
    }
    __syncthreads();
    const float mu = sbc * (1.f / H_);

    float dx = v.x - mu, dy = v.y - mu, dz = v.z - mu, dw = v.w - mu;
    float qq = dx * dx + dy * dy + dz * dz + dw * dw;
#pragma unroll
    for (int o = 16; o > 0; o >>= 1) qq += __shfl_xor_sync(~0u, qq, o);
    if (lane == 0) sred[wid] = qq;
    __syncthreads();
    if (tid == 0) {
        float t = 0.f;
#pragma unroll
        for (int i = 0; i < 8; i++) t += sred[i];
        sbc = t;
    }
    __syncthreads();
    const float rstd = rsqrtf(sbc * (1.f / H_) + 1e-12f);

    float4 gg = ((const float4*)g)[tid];
    float4 bt = ((const float4*)bb)[tid];
    float4 o;
    o.x = dx * rstd * gg.x + bt.x;
    o.y = dy * rstd * gg.y + bt.y;
    o.z = dz * rstd * gg.z + bt.z;
    o.w = dw * rstd * gg.w + bt.w;
    ((float4*)(out + row * H_))[tid] = o;
}

// ---------------- launch -----------------------------------------------------------
extern "C" void kernel_launch(void* const* d_in, const int* in_sizes, int n_in,
                              void* d_out, int out_size)
{
    (void)in_sizes; (void)n_in; (void)out_size;
    const float* x    = (const float*)d_in[0];
    const float* mask = (const float*)d_in[1];
    const float* Wq   = (const float*)d_in[2];
    const float* bq   = (const float*)d_in[3];
    const float* Wk   = (const float*)d_in[4];
    const float* bk   = (const float*)d_in[5];
    const float* Wv   = (const float*)d_in[6];
    const float* bv   = (const float*)d_in[7];
    const float* de   = (const float*)d_in[8];
    const float* Wo   = (const float*)d_in[9];
    const float* bo   = (const float*)d_in[10];
    const float* lng  = (const float*)d_in[11];
    const float* lnb  = (const float*)d_in[12];
    float* out = (float*)d_out;

    float* y;
    cudaGetSymbolAddress((void**)&y, g_y);

    __nv_bfloat16 *xh, *xl, *wqh, *wql, *wkh, *wkl, *wvh, *wvl, *woh, *wol;
    __nv_bfloat16 *qh, *ql, *kh, *kl, *vh, *vl, *deh, *del, *ch, *cl;
    cudaGetSymbolAddress((void**)&xh, g_xh);   cudaGetSymbolAddress((void**)&xl, g_xl);
    cudaGetSymbolAddress((void**)&wqh, g_wqh); cudaGetSymbolAddress((void**)&wql, g_wql);
    cudaGetSymbolAddress((void**)&wkh, g_wkh); cudaGetSymbolAddress((void**)&wkl, g_wkl);
    cudaGetSymbolAddress((void**)&wvh, g_wvh); cudaGetSymbolAddress((void**)&wvl, g_wvl);
    cudaGetSymbolAddress((void**)&woh, g_woh); cudaGetSymbolAddress((void**)&wol, g_wol);
    cudaGetSymbolAddress((void**)&qh, g_qh);   cudaGetSymbolAddress((void**)&ql, g_ql);
    cudaGetSymbolAddress((void**)&kh, g_kh);   cudaGetSymbolAddress((void**)&kl, g_kl);
    cudaGetSymbolAddress((void**)&vh, g_vh);   cudaGetSymbolAddress((void**)&vl, g_vl);
    cudaGetSymbolAddress((void**)&deh, g_deh); cudaGetSymbolAddress((void**)&del, g_del);
    cudaGetSymbolAddress((void**)&ch, g_ch);   cudaGetSymbolAddress((void**)&cl, g_cl);

    cudaFuncSetAttribute(gemm_mma2<1>, cudaFuncAttributeMaxDynamicSharedMemorySize, GSM_TOTAL);
    cudaFuncSetAttribute(gemm_mma2<2>, cudaFuncAttributeMaxDynamicSharedMemorySize, GSM_TOTAL);
    cudaFuncSetAttribute(fused_attn, cudaFuncAttributeMaxDynamicSharedMemorySize, FSM_TOTAL);

    const int NX4 = BS_ * H_ / 4;
    const int NW4 = H_ * H_ / 4;
    split_kernel<<<NX4 / 256, 256>>>(x, xh, xl, NX4);
    split4_kernel<<<dim3(NW4 / 256, 4), 256>>>(Wq, Wk, Wv, Wo,
                                               wqh, wql, wkh, wkl,
                                               wvh, wvl, woh, wol);
    const int ND4 = 2047 * 64 / 4;
    split_kernel<<<(ND4 + 255) / 256, 256>>>(de, deh, del, ND4);

    gemm_mma2<2><<<dim3(H_ / 128, BS_ / 128, 3), 256, GSM_TOTAL>>>(
        xh, xl, wqh, wql, wkh, wkl, wvh, wvl, bq, bk, bv,
        qh, kh, vh, ql, kl, vl, nullptr);

    fused_attn<<<dim3(S_ / 64, BH_), 256, FSM_TOTAL>>>(
        qh, ql, kh, kl, vh, vl, deh, del, mask, ch, cl);

    gemm_mma2<1><<<dim3(H_ / 128, BS_ / 128, 1), 256, GSM_TOTAL>>>(
        ch, cl, woh, wol, woh, wol, woh, wol, bo, bo, bo,
        y, y, y, nullptr, nullptr, nullptr, x);

    ln_kernel<<<BS_, 256>>>(y, lng, lnb, out);
}